// round 2
// baseline (speedup 1.0000x reference)
#include <cuda_runtime.h>
#include <math.h>

// ---------------------------------------------------------------------------
// Scratch (static __device__ arrays — allocation-free per harness rules).
// Referenced DIRECTLY from device code; no cudaGetSymbolAddress on the host.
// ---------------------------------------------------------------------------
__device__ float g_out1[8u*256u*64u*64u];    // conv1 output, 32 MB
__device__ float g_up1 [8u*256u*128u*128u];  // upsampled conv1 output, 128 MB
__device__ float g_skip[8u*128u*64u*64u];    // 1x1-conv skip at 64-res, 8 MB

// ---------------------------------------------------------------------------
// Packed f32x2 helpers (Blackwell FFMA2 — 2 MACs per instruction)
// ---------------------------------------------------------------------------
__device__ __forceinline__ void fma2(unsigned long long &d,
                                     unsigned long long a,
                                     unsigned long long b) {
    asm("fma.rn.f32x2 %0, %1, %2, %0;" : "+l"(d) : "l"(a), "l"(b));
}
__device__ __forceinline__ void unpack2(unsigned long long v, float &lo, float &hi) {
    asm("mov.b64 {%0, %1}, %2;" : "=f"(lo), "=f"(hi) : "l"(v));
}

// ---------------------------------------------------------------------------
// Fused 3x3 conv (stride 1, pad 1) + scale + bias + LeakyReLU(0.2)*sqrt(2)
// FUSE=false (conv1): in = param (x), out = g_out1.
// FUSE=true  (conv2): in = g_up1, out = param, adds bilinear-gathered g_skip
//                     and applies the final /sqrt(2).
// Tile: 32x (4/thread) x 8y x 32co (8/thread). 256 threads.
// ---------------------------------------------------------------------------
template<int H, int W, int CIN, int COUT, bool FUSE>
__global__ __launch_bounds__(256)
void conv3x3_k(const float* __restrict__ in_param,
               const float* __restrict__ wgt,
               const float* __restrict__ bias,
               float* __restrict__ out_param, float scale)
{
    const float* __restrict__ in  = FUSE ? (const float*)g_up1 : in_param;
    float* __restrict__       out = FUSE ? out_param : (float*)g_out1;

    constexpr int CI  = 8;
    constexpr int TW  = 32, TH = 8, TCO = 32;

    __shared__ __align__(16) float2 s_in[CI][TH+2][TW+4];  // duplicated {v,v}
    __shared__ __align__(16) float  s_w[CI][9][TCO];       // [ci][tap][co]

    const int t  = threadIdx.x;
    const int tx = t & 7;          // 8 threads * 4 px = 32 px in x
    const int ty = (t >> 3) & 7;   // 8 rows
    const int tz = t >> 6;         // 4 * 8 co = 32 co

    const int ntx    = W / TW;
    const int tile_x = blockIdx.x % ntx;
    const int tile_y = blockIdx.x / ntx;
    const int n      = blockIdx.z;
    const int co_blk = blockIdx.y * TCO;

    const int x0  = tile_x * TW;
    const int y0  = tile_y * TH;
    const int xb  = tx * 4;
    const int py  = y0 + ty;
    const int px0 = x0 + xb;
    const int co0 = co_blk + tz * 8;

    float bq[8];
    #pragma unroll
    for (int q = 0; q < 8; q++) bq[q] = bias[co0 + q];

    unsigned long long acc[4][4];
    #pragma unroll
    for (int p = 0; p < 4; p++)
        #pragma unroll
        for (int q = 0; q < 4; q++) acc[p][q] = 0ull;

    for (int cc = 0; cc < CIN; cc += CI) {
        __syncthreads();
        // ---- load input tile (zero-padded halo), duplicated for f32x2 ----
        for (int idx = t; idx < CI * 10 * 34; idx += 256) {
            int ci  = idx / 340;
            int r   = idx - ci * 340;
            int row = r / 34;
            int col = r - row * 34;
            int gy  = y0 + row - 1, gx = x0 + col - 1;
            float v = 0.f;
            if (gy >= 0 && gy < H && gx >= 0 && gx < W)
                v = in[(n * CIN + cc + ci) * (H * W) + gy * W + gx];
            s_in[ci][row][col] = make_float2(v, v);
        }
        // ---- load weights transposed to [ci][tap][co] ----
        for (int idx = t; idx < TCO * CI * 9; idx += 256) {
            int co  = idx / 72;
            int r   = idx - co * 72;
            int ci  = r / 9;
            int tap = r - ci * 9;
            s_w[ci][tap][co] = wgt[(co_blk + co) * (CIN * 9) + (cc + ci) * 9 + tap];
        }
        __syncthreads();

        #pragma unroll
        for (int ci = 0; ci < CI; ci++) {
            #pragma unroll
            for (int dy = 0; dy < 3; dy++) {
                const ulonglong2* ip =
                    reinterpret_cast<const ulonglong2*>(&s_in[ci][ty + dy][xb]);
                ulonglong2 a0 = ip[0], a1 = ip[1], a2 = ip[2];
                unsigned long long win[6] = {a0.x, a0.y, a1.x, a1.y, a2.x, a2.y};
                #pragma unroll
                for (int dx = 0; dx < 3; dx++) {
                    const ulonglong2* wp =
                        reinterpret_cast<const ulonglong2*>(&s_w[ci][dy * 3 + dx][tz * 8]);
                    ulonglong2 w0 = wp[0], w1 = wp[1];
                    unsigned long long wv[4] = {w0.x, w0.y, w1.x, w1.y};
                    #pragma unroll
                    for (int p = 0; p < 4; p++)
                        #pragma unroll
                        for (int q = 0; q < 4; q++)
                            fma2(acc[p][q], win[p + dx], wv[q]);
                }
            }
        }
    }

    // ---- epilogue ----
    int ya = 0, yb2 = 0; float wya = 0.f, wyb = 0.f;
    if (FUSE) {
        int jy = py >> 1; bool ev = !(py & 1);
        ya  = ev ? max(jy - 1, 0) : jy;
        yb2 = ev ? jy : min(jy + 1, 63);
        wya = ev ? 0.25f : 0.75f;
        wyb = ev ? 0.75f : 0.25f;
    }
    #pragma unroll
    for (int p = 0; p < 4; p++) {
        int ox = px0 + p;
        int xa = 0, xb2 = 0; float wxa = 0.f, wxb = 0.f;
        if (FUSE) {
            int jx = ox >> 1; bool evx = !(ox & 1);
            xa  = evx ? max(jx - 1, 0) : jx;
            xb2 = evx ? jx : min(jx + 1, 63);
            wxa = evx ? 0.25f : 0.75f;
            wxb = evx ? 0.75f : 0.25f;
        }
        #pragma unroll
        for (int q2 = 0; q2 < 4; q2++) {
            float v0, v1;
            unpack2(acc[p][q2], v0, v1);
            float vv[2] = {v0, v1};
            #pragma unroll
            for (int h = 0; h < 2; h++) {
                int co = co0 + 2 * q2 + h;
                float v = vv[h] * scale + bq[2 * q2 + h];
                v = (v >= 0.f ? v : 0.2f * v) * 1.41421356237309515f;
                if (FUSE) {
                    const float* S = (const float*)g_skip + (n * COUT + co) * 4096;
                    float sv = wya * (wxa * S[ya  * 64 + xa] + wxb * S[ya  * 64 + xb2])
                             + wyb * (wxa * S[yb2 * 64 + xa] + wxb * S[yb2 * 64 + xb2]);
                    v = (v + sv) * 0.70710678118654752f;
                }
                out[(n * COUT + co) * (H * W) + py * W + ox] = v;
            }
        }
    }
}

// ---------------------------------------------------------------------------
// Bilinear 2x upsample, g_out1 (64x64) -> g_up1 (128x128)
// (align_corners=False half-pixel convention, edge clamp — matches jax.image.resize)
// ---------------------------------------------------------------------------
__global__ __launch_bounds__(256)
void upsample2x_k()
{
    int idx = blockIdx.x * 256 + threadIdx.x;
    int ox = idx & 127, oy = (idx >> 7) & 127, nc = idx >> 14;

    int jy = oy >> 1; bool evy = !(oy & 1);
    int ya  = evy ? max(jy - 1, 0) : jy;
    int yb2 = evy ? jy : min(jy + 1, 63);
    float wya = evy ? 0.25f : 0.75f, wyb = evy ? 0.75f : 0.25f;

    int jx = ox >> 1; bool evx = !(ox & 1);
    int xa  = evx ? max(jx - 1, 0) : jx;
    int xb2 = evx ? jx : min(jx + 1, 63);
    float wxa = evx ? 0.25f : 0.75f, wxb = evx ? 0.75f : 0.25f;

    const float* p = (const float*)g_out1 + nc * 4096;
    g_up1[idx] = wya * (wxa * p[ya  * 64 + xa] + wxb * p[ya  * 64 + xb2])
               + wyb * (wxa * p[yb2 * 64 + xa] + wxb * p[yb2 * 64 + xb2]);
}

// ---------------------------------------------------------------------------
// 1x1 equalized conv at 64-res: g_skip[n,co,p] = (1/16) * sum_ci x * w
// (1x1 conv commutes with bilinear upsample — skip computed at 64x64.)
// Tile: 256 px (4/thread, stride-64 interleave) x 32 co (8/thread). 256 thr.
// ---------------------------------------------------------------------------
__global__ __launch_bounds__(256)
void skip1x1_k(const float* __restrict__ x, const float* __restrict__ wsk)
{
    __shared__ __align__(16) float2 s_x[8][256];
    __shared__ __align__(16) float  s_w[8][32];

    const int t   = threadIdx.x;
    const int pxt = t & 63;
    const int cot = t >> 6;
    const int n = blockIdx.z, cotile = blockIdx.y, pxtile = blockIdx.x;
    const int pxbase = pxtile * 256;

    unsigned long long acc[4][4];
    #pragma unroll
    for (int p = 0; p < 4; p++)
        #pragma unroll
        for (int q = 0; q < 4; q++) acc[p][q] = 0ull;

    for (int cc = 0; cc < 256; cc += 8) {
        __syncthreads();
        for (int idx = t; idx < 8 * 256; idx += 256) {
            int ci = idx >> 8, px = idx & 255;
            float v = x[(n * 256 + cc + ci) * 4096 + pxbase + px];
            s_x[ci][px] = make_float2(v, v);
        }
        {   // 256 weight elements, one per thread
            int ci = t >> 5, co = t & 31;
            s_w[ci][co] = wsk[(cotile * 32 + co) * 256 + cc + ci];
        }
        __syncthreads();
        #pragma unroll
        for (int ci = 0; ci < 8; ci++) {
            unsigned long long xv[4];
            #pragma unroll
            for (int p = 0; p < 4; p++)
                xv[p] = *reinterpret_cast<const unsigned long long*>(&s_x[ci][pxt + p * 64]);
            const ulonglong2* wp =
                reinterpret_cast<const ulonglong2*>(&s_w[ci][cot * 8]);
            ulonglong2 w0 = wp[0], w1 = wp[1];
            unsigned long long wv[4] = {w0.x, w0.y, w1.x, w1.y};
            #pragma unroll
            for (int p = 0; p < 4; p++)
                #pragma unroll
                for (int q = 0; q < 4; q++)
                    fma2(acc[p][q], xv[p], wv[q]);
        }
    }

    #pragma unroll
    for (int p = 0; p < 4; p++) {
        int px = pxbase + pxt + p * 64;
        #pragma unroll
        for (int q2 = 0; q2 < 4; q2++) {
            float v0, v1;
            unpack2(acc[p][q2], v0, v1);
            int cob = cotile * 32 + cot * 8 + 2 * q2;
            g_skip[(n * 128 + cob    ) * 4096 + px] = v0 * 0.0625f;
            g_skip[(n * 128 + cob + 1) * 4096 + px] = v1 * 0.0625f;
        }
    }
}

// ---------------------------------------------------------------------------
// kernel_launch — kernel launches ONLY (graph-capture safe, allocation-free)
// ---------------------------------------------------------------------------
extern "C" void kernel_launch(void* const* d_in, const int* in_sizes, int n_in,
                              void* d_out, int out_size)
{
    const float* x   = (const float*)d_in[0];
    const float* w1  = (const float*)d_in[1];
    const float* b1  = (const float*)d_in[2];
    const float* w2  = (const float*)d_in[3];
    const float* b2  = (const float*)d_in[4];
    const float* wsk = (const float*)d_in[5];
    float* out = (float*)d_out;

    const float scale3 = 1.0f / 48.0f;  // 1/sqrt(256*9)

    // conv1: 3x3 (256->256) @64x64 + FusedLeakyReLU -> g_out1
    conv3x3_k<64, 64, 256, 256, false>
        <<<dim3(16, 8, 8), 256>>>(x, w1, b1, nullptr, scale3);

    // bilinear x2: g_out1 -> g_up1
    upsample2x_k<<<(8 * 256 * 128 * 128) / 256, 256>>>();

    // skip: 1x1 (256->128) @64x64 -> g_skip
    skip1x1_k<<<dim3(16, 4, 8), 256>>>(x, wsk);

    // conv2: 3x3 (256->128) @128x128 + FusedLeakyReLU + upsampled-skip add -> out
    conv3x3_k<128, 128, 256, 128, true>
        <<<dim3(64, 4, 8), 256>>>(nullptr, w2, b2, out, scale3);
}

// round 4
// speedup vs baseline: 1.5716x; 1.5716x over previous
#include <cuda_runtime.h>
#include <math.h>

typedef unsigned long long ull;

// ---------------------------------------------------------------------------
// Scratch (static __device__ arrays — allocation-free per harness rules)
// ---------------------------------------------------------------------------
__device__ float g_out1[8u*256u*64u*64u];    // conv1 output
__device__ float g_up1 [8u*256u*128u*128u];  // upsampled conv1 output
__device__ float g_skip[8u*128u*64u*64u];    // 1x1-conv skip at 64-res
__device__ float g_w1t [256*9*256];          // w1 transposed [ci*9+tap][co], pre-scaled
__device__ float g_w2t [256*9*128];          // w2 transposed, pre-scaled
__device__ float g_wskt[256*128];            // wsk transposed [ci][co], pre-scaled

// ---------------------------------------------------------------------------
// Packed f32x2 helpers
// ---------------------------------------------------------------------------
__device__ __forceinline__ void fma2(ull &d, ull a, ull b) {
    asm("fma.rn.f32x2 %0, %1, %2, %0;" : "+l"(d) : "l"(a), "l"(b));
}
__device__ __forceinline__ ull dup2(float v) {
    ull r; asm("mov.b64 %0, {%1, %1};" : "=l"(r) : "f"(v)); return r;
}
__device__ __forceinline__ void unpack2(ull v, float &lo, float &hi) {
    asm("mov.b64 {%0, %1}, %2;" : "=f"(lo), "=f"(hi) : "l"(v));
}

// ---------------------------------------------------------------------------
// Weight prep: transpose + pre-apply equalized-lr scale (runs every call)
// ---------------------------------------------------------------------------
__global__ __launch_bounds__(256)
void prep_weights_k(const float* __restrict__ w1, const float* __restrict__ w2,
                    const float* __restrict__ wsk)
{
    const float SC3 = 1.0f / 48.0f;   // 1/sqrt(256*9)
    const float SC1 = 1.0f / 16.0f;   // 1/sqrt(256)
    int i = blockIdx.x * 256 + threadIdx.x;
    if (i < 256*9*256) {            // g_w1t[rt*256+co] = w1[co][rt]*SC3
        int co = i & 255, rt = i >> 8;
        g_w1t[i] = w1[co * 2304 + rt] * SC3;
    }
    if (i < 256*9*128) {            // g_w2t[rt*128+co] = w2[co][rt]*SC3
        int co = i & 127, rt = i >> 7;
        g_w2t[i] = w2[co * 2304 + rt] * SC3;
    }
    if (i < 256*128) {              // g_wskt[ci*128+co] = wsk[co][ci]*SC1
        int co = i & 127, ci = i >> 7;
        g_wskt[i] = wsk[co * 256 + ci] * SC1;
    }
}

// ---------------------------------------------------------------------------
// 3x3 conv (stride 1, pad 1) + bias + LeakyReLU(0.2)*sqrt(2).
// Weights pre-scaled. FUSE adds the bilinear-gathered skip and final /sqrt(2).
// Tile: 32x x 8y x 64co. Thread: 8 px (x) x 8 co. 256 threads.
// ---------------------------------------------------------------------------
template<int H, int W, int CIN, int COUT, bool FUSE>
__global__ __launch_bounds__(256)
void conv3x3_v3(const float* __restrict__ in_param,
                const float* __restrict__ bias,
                float* __restrict__ out_param)
{
    const float* __restrict__ in  = FUSE ? (const float*)g_up1 : in_param;
    const float* __restrict__ wt  = FUSE ? (const float*)g_w2t : (const float*)g_w1t;
    float* __restrict__       out = FUSE ? out_param : (float*)g_out1;

    // s_in cols: c in [0..32] <-> gx = x0+c ; col 34 holds left halo gx = x0-1
    __shared__ __align__(16) float s_in[8][10][36];
    __shared__ __align__(16) float s_w[8 * 9 * 64];   // [ci][tap][64co]

    const int t  = threadIdx.x;
    const int tx = t & 3;            // 4 groups * 8 px = 32 px
    const int ty = (t >> 2) & 7;     // 8 rows
    const int tz = t >> 5;           // 8 groups * 8 co = 64 co

    const int ntx    = W / 32;
    const int tile_x = blockIdx.x % ntx;
    const int tile_y = blockIdx.x / ntx;
    const int n      = blockIdx.z;
    const int co_blk = blockIdx.y * 64;

    const int x0  = tile_x * 32;
    const int y0  = tile_y * 8;
    const int xb  = tx * 8;
    const int py  = y0 + ty;
    const int px0 = x0 + xb;
    const int co0 = co_blk + tz * 8;

    float bq[8];
    #pragma unroll
    for (int q = 0; q < 8; q++) bq[q] = bias[co0 + q];

    ull acc[8][4];
    #pragma unroll
    for (int p = 0; p < 8; p++)
        #pragma unroll
        for (int q = 0; q < 4; q++) acc[p][q] = 0ull;

    for (int cc = 0; cc < CIN; cc += 8) {
        __syncthreads();
        // ---- input fill: interior as float4 (640 slots) ----
        for (int s = t; s < 640; s += 256) {
            int row_id = s >> 3, j = s & 7;
            int ci = row_id / 10, r = row_id - ci * 10;
            int gy = y0 + r - 1;
            float4 v = make_float4(0.f, 0.f, 0.f, 0.f);
            if ((unsigned)gy < (unsigned)H)
                v = *(const float4*)&in[((n * CIN + cc + ci) * H + gy) * W + x0 + j * 4];
            *(float4*)&s_in[ci][r][j * 4] = v;
        }
        // ---- input fill: edge columns (160 slots) ----
        if (t < 160) {
            int row_id = t >> 1, side = t & 1;
            int ci = row_id / 10, r = row_id - ci * 10;
            int gy = y0 + r - 1;
            int gx  = side ? (x0 + 32) : (x0 - 1);
            int col = side ? 32 : 34;
            float v = 0.f;
            if ((unsigned)gy < (unsigned)H && (unsigned)gx < (unsigned)W)
                v = in[((n * CIN + cc + ci) * H + gy) * W + gx];
            s_in[ci][r][col] = v;
        }
        // ---- weight fill: float4 (1152 slots), already transposed ----
        for (int s = t; s < 1152; s += 256) {
            int row = s >> 4, j = s & 15;   // row = ci*9+tap
            float4 v = *(const float4*)&wt[(cc * 9 + row) * COUT + co_blk + j * 4];
            *(float4*)&s_w[row * 64 + j * 4] = v;
        }
        __syncthreads();

        #pragma unroll 1
        for (int ci = 0; ci < 8; ci++) {
            #pragma unroll
            for (int dy = 0; dy < 3; dy++) {
                const float* rowp = &s_in[ci][ty + dy][0];
                float4 m0 = *(const float4*)&rowp[xb];
                float4 m1 = *(const float4*)&rowp[xb + 4];
                float wl = rowp[tx == 0 ? 34 : xb - 1];
                float wr = rowp[xb + 8];
                ull d[10];
                d[0] = dup2(wl);
                d[1] = dup2(m0.x); d[2] = dup2(m0.y); d[3] = dup2(m0.z); d[4] = dup2(m0.w);
                d[5] = dup2(m1.x); d[6] = dup2(m1.y); d[7] = dup2(m1.z); d[8] = dup2(m1.w);
                d[9] = dup2(wr);
                #pragma unroll
                for (int dx = 0; dx < 3; dx++) {
                    const ulonglong2* wp =
                        (const ulonglong2*)&s_w[(ci * 9 + dy * 3 + dx) * 64 + tz * 8];
                    ulonglong2 w0 = wp[0], w1 = wp[1];
                    ull wv[4] = {w0.x, w0.y, w1.x, w1.y};
                    #pragma unroll
                    for (int p = 0; p < 8; p++)
                        #pragma unroll
                        for (int q = 0; q < 4; q++)
                            fma2(acc[p][q], d[p + dx], wv[q]);
                }
            }
        }
    }

    // ---- epilogue ----
    int ya = 0, yb2 = 0; float wya = 0.f, wyb = 0.f; int jxb = 0;
    if (FUSE) {
        int jy = py >> 1; bool ev = !(py & 1);
        ya  = ev ? max(jy - 1, 0) : jy;
        yb2 = ev ? jy : min(jy + 1, 63);
        wya = ev ? 0.25f : 0.75f;
        wyb = ev ? 0.75f : 0.25f;
        jxb = (x0 >> 1) + tx * 4 - 1;
    }

    const long obase = (long)(n * COUT) * (H * W) + py * W + px0;
    #pragma unroll
    for (int q2 = 0; q2 < 4; q2++) {
        #pragma unroll
        for (int h = 0; h < 2; h++) {
            int co = co0 + 2 * q2 + h;
            float v[8];
            #pragma unroll
            for (int p = 0; p < 8; p++) {
                float lo, hi;
                unpack2(acc[p][q2], lo, hi);
                float val = (h ? hi : lo) + bq[2 * q2 + h];
                v[p] = (val >= 0.f ? val : 0.2f * val) * 1.41421356237309515f;
            }
            if (FUSE) {
                const float* S = (const float*)g_skip + (n * COUT + co) * 4096;
                float rA[6], rB[6];
                #pragma unroll
                for (int k = 0; k < 6; k++) {
                    int c = min(max(jxb + k, 0), 63);
                    rA[k] = S[ya  * 64 + c];
                    rB[k] = S[yb2 * 64 + c];
                }
                #pragma unroll
                for (int p = 0; p < 8; p++) {
                    int k0 = p >> 1;
                    float sxA, sxB;
                    if ((p & 1) == 0) {
                        sxA = 0.25f * rA[k0] + 0.75f * rA[k0 + 1];
                        sxB = 0.25f * rB[k0] + 0.75f * rB[k0 + 1];
                    } else {
                        sxA = 0.75f * rA[k0 + 1] + 0.25f * rA[k0 + 2];
                        sxB = 0.75f * rB[k0 + 1] + 0.25f * rB[k0 + 2];
                    }
                    float sv = wya * sxA + wyb * sxB;
                    v[p] = (v[p] + sv) * 0.70710678118654752f;
                }
            }
            float* op = out + obase + (long)co * (H * W);
            *(float4*)&op[0] = make_float4(v[0], v[1], v[2], v[3]);
            *(float4*)&op[4] = make_float4(v[4], v[5], v[6], v[7]);
        }
    }
}

// ---------------------------------------------------------------------------
// Bilinear 2x upsample, g_out1 (64) -> g_up1 (128); 4 px per thread.
// ---------------------------------------------------------------------------
__global__ __launch_bounds__(256)
void upsample2x_v3()
{
    int idx = blockIdx.x * 256 + threadIdx.x;         // 8.39M threads
    int oxg = idx & 31;                               // 32 groups of 4 px
    int oy  = (idx >> 5) & 127;
    int nc  = idx >> 12;

    int jy = oy >> 1; bool ev = !(oy & 1);
    int ya  = ev ? max(jy - 1, 0) : jy;
    int yb2 = ev ? jy : min(jy + 1, 63);
    float wya = ev ? 0.25f : 0.75f, wyb = ev ? 0.75f : 0.25f;

    int jxb = oxg * 2 - 1;
    const float* p = (const float*)g_out1 + nc * 4096;
    float rA[4], rB[4];
    #pragma unroll
    for (int k = 0; k < 4; k++) {
        int c = min(max(jxb + k, 0), 63);
        rA[k] = p[ya  * 64 + c];
        rB[k] = p[yb2 * 64 + c];
    }
    float o[4];
    #pragma unroll
    for (int pp = 0; pp < 4; pp++) {
        int k0 = pp >> 1;
        float sxA, sxB;
        if ((pp & 1) == 0) {
            sxA = 0.25f * rA[k0] + 0.75f * rA[k0 + 1];
            sxB = 0.25f * rB[k0] + 0.75f * rB[k0 + 1];
        } else {
            sxA = 0.75f * rA[k0 + 1] + 0.25f * rA[k0 + 2];
            sxB = 0.75f * rB[k0 + 1] + 0.25f * rB[k0 + 2];
        }
        o[pp] = wya * sxA + wyb * sxB;
    }
    *(float4*)&g_up1[(nc * 128 + oy) * 128 + oxg * 4] =
        make_float4(o[0], o[1], o[2], o[3]);
}

// ---------------------------------------------------------------------------
// 1x1 equalized conv at 64-res -> g_skip (weights pre-scaled).
// Tile: 256 px x 64 co. Thread: 8 px (two float4 groups) x 8 co.
// ---------------------------------------------------------------------------
__global__ __launch_bounds__(256)
void skip1x1_v3(const float* __restrict__ x)
{
    __shared__ __align__(16) float s_x[8][260];
    __shared__ __align__(16) float s_w[8 * 64];

    const int t  = threadIdx.x;
    const int tx = t & 31;
    const int tz = t >> 5;
    const int n = blockIdx.z, cob = blockIdx.y * 64, pxb = blockIdx.x * 256;

    ull acc[8][4];
    #pragma unroll
    for (int p = 0; p < 8; p++)
        #pragma unroll
        for (int q = 0; q < 4; q++) acc[p][q] = 0ull;

    for (int cc = 0; cc < 256; cc += 8) {
        __syncthreads();
        for (int s = t; s < 512; s += 256) {      // input: 8ci x 64 float4
            int ci = s >> 6, j = s & 63;
            float4 v = *(const float4*)&x[(n * 256 + cc + ci) * 4096 + pxb + j * 4];
            *(float4*)&s_x[ci][j * 4] = v;
        }
        if (t < 128) {                            // weights: 8ci x 16 float4
            int ci = t >> 4, j = t & 15;
            float4 v = *(const float4*)&g_wskt[(cc + ci) * 128 + cob + j * 4];
            *(float4*)&s_w[ci * 64 + j * 4] = v;
        }
        __syncthreads();
        #pragma unroll 1
        for (int ci = 0; ci < 8; ci++) {
            float4 a0 = *(const float4*)&s_x[ci][tx * 4];
            float4 a1 = *(const float4*)&s_x[ci][128 + tx * 4];
            ull d[8] = {dup2(a0.x), dup2(a0.y), dup2(a0.z), dup2(a0.w),
                        dup2(a1.x), dup2(a1.y), dup2(a1.z), dup2(a1.w)};
            const ulonglong2* wp = (const ulonglong2*)&s_w[ci * 64 + tz * 8];
            ulonglong2 w0 = wp[0], w1 = wp[1];
            ull wv[4] = {w0.x, w0.y, w1.x, w1.y};
            #pragma unroll
            for (int p = 0; p < 8; p++)
                #pragma unroll
                for (int q = 0; q < 4; q++)
                    fma2(acc[p][q], d[p], wv[q]);
        }
    }

    #pragma unroll
    for (int q2 = 0; q2 < 4; q2++) {
        #pragma unroll
        for (int h = 0; h < 2; h++) {
            int co = cob + tz * 8 + 2 * q2 + h;
            float v[8];
            #pragma unroll
            for (int p = 0; p < 8; p++) {
                float lo, hi; unpack2(acc[p][q2], lo, hi);
                v[p] = h ? hi : lo;
            }
            float* op = (float*)g_skip + (n * 128 + co) * 4096 + pxb;
            *(float4*)&op[tx * 4]       = make_float4(v[0], v[1], v[2], v[3]);
            *(float4*)&op[128 + tx * 4] = make_float4(v[4], v[5], v[6], v[7]);
        }
    }
}

// ---------------------------------------------------------------------------
// kernel_launch — kernel launches only (graph-capturable, allocation-free)
// ---------------------------------------------------------------------------
extern "C" void kernel_launch(void* const* d_in, const int* in_sizes, int n_in,
                              void* d_out, int out_size)
{
    const float* x   = (const float*)d_in[0];
    const float* w1  = (const float*)d_in[1];
    const float* b1  = (const float*)d_in[2];
    const float* w2  = (const float*)d_in[3];
    const float* b2  = (const float*)d_in[4];
    const float* wsk = (const float*)d_in[5];
    float* out = (float*)d_out;

    // weight transpose + scale (2304 blocks covers the largest table)
    prep_weights_k<<<2304, 256>>>(w1, w2, wsk);

    // conv1: 3x3 (256->256) @64 -> g_out1.  tiles: 2x8=16, co: 4, n: 8
    conv3x3_v3<64, 64, 256, 256, false><<<dim3(16, 4, 8), 256>>>(x, b1, nullptr);

    // bilinear x2: g_out1 -> g_up1
    upsample2x_v3<<<(8 * 256 * 128 * 128) / (4 * 256), 256>>>();

    // skip 1x1 @64 -> g_skip.  px: 16, co: 2, 8
    skip1x1_v3<<<dim3(16, 2, 8), 256>>>(x);

    // conv2: 3x3 (256->128) @128 + skip fuse -> out.  tiles: 4x16=64, co: 2, n: 8
    conv3x3_v3<128, 128, 256, 128, true><<<dim3(64, 2, 8), 256>>>(nullptr, b2, out);
}

// round 5
// speedup vs baseline: 1.5743x; 1.0017x over previous
#include <cuda_runtime.h>
#include <math.h>

typedef unsigned long long ull;

// ---------------------------------------------------------------------------
// Scratch (static __device__ arrays — allocation-free per harness rules)
// ---------------------------------------------------------------------------
__device__ float g_out1[8u*256u*64u*64u];    // conv1 output
__device__ float g_up1 [8u*256u*128u*128u];  // upsampled conv1 output
__device__ float g_skip[8u*128u*64u*64u];    // 1x1-conv skip at 64-res
__device__ float g_w1t [256*9*256];          // w1 transposed [ci*9+tap][co], pre-scaled
__device__ float g_w2t [256*9*128];          // w2 transposed, pre-scaled
__device__ float g_wskt[256*128];            // wsk transposed [ci][co], pre-scaled

// ---------------------------------------------------------------------------
// Packed f32x2 helpers
// ---------------------------------------------------------------------------
__device__ __forceinline__ void fma2(ull &d, ull a, ull b) {
    asm("fma.rn.f32x2 %0, %1, %2, %0;" : "+l"(d) : "l"(a), "l"(b));
}
__device__ __forceinline__ ull dup2(float v) {
    ull r; asm("mov.b64 %0, {%1, %1};" : "=l"(r) : "f"(v)); return r;
}
__device__ __forceinline__ void unpack2(ull v, float &lo, float &hi) {
    asm("mov.b64 {%0, %1}, %2;" : "=f"(lo), "=f"(hi) : "l"(v));
}

// ---------------------------------------------------------------------------
// Weight prep: transpose + pre-apply equalized-lr scale (runs every call)
// ---------------------------------------------------------------------------
__global__ __launch_bounds__(256)
void prep_weights_k(const float* __restrict__ w1, const float* __restrict__ w2,
                    const float* __restrict__ wsk)
{
    const float SC3 = 1.0f / 48.0f;   // 1/sqrt(256*9)
    const float SC1 = 1.0f / 16.0f;   // 1/sqrt(256)
    int i = blockIdx.x * 256 + threadIdx.x;
    if (i < 256*9*256) {            // g_w1t[rt*256+co] = w1[co][rt]*SC3
        int co = i & 255, rt = i >> 8;
        g_w1t[i] = w1[co * 2304 + rt] * SC3;
    }
    if (i < 256*9*128) {            // g_w2t[rt*128+co] = w2[co][rt]*SC3
        int co = i & 127, rt = i >> 7;
        g_w2t[i] = w2[co * 2304 + rt] * SC3;
    }
    if (i < 256*128) {              // g_wskt[ci*128+co] = wsk[co][ci]*SC1
        int co = i & 127, ci = i >> 7;
        g_wskt[i] = wsk[co * 256 + ci] * SC1;
    }
}

// ---------------------------------------------------------------------------
// 3x3 conv (stride 1, pad 1) + bias + LeakyReLU(0.2)*sqrt(2).
// Weights pre-scaled. FUSE adds the bilinear-gathered skip and final /sqrt(2).
// Tile: 32x x 8y x 64co. Thread: 8 px (x) x 8 co. 256 threads.
// ---------------------------------------------------------------------------
template<int H, int W, int CIN, int COUT, bool FUSE>
__global__ __launch_bounds__(256)
void conv3x3_v3(const float* __restrict__ in_param,
                const float* __restrict__ bias,
                float* __restrict__ out_param)
{
    const float* __restrict__ in  = FUSE ? (const float*)g_up1 : in_param;
    const float* __restrict__ wt  = FUSE ? (const float*)g_w2t : (const float*)g_w1t;
    float* __restrict__       out = FUSE ? out_param : (float*)g_out1;

    // s_in cols: c in [0..32] <-> gx = x0+c ; col 34 holds left halo gx = x0-1
    __shared__ __align__(16) float s_in[8][10][36];
    __shared__ __align__(16) float s_w[8 * 9 * 64];   // [ci][tap][64co]

    const int t  = threadIdx.x;
    const int tx = t & 3;            // 4 groups * 8 px = 32 px
    const int ty = (t >> 2) & 7;     // 8 rows
    const int tz = t >> 5;           // 8 groups * 8 co = 64 co

    const int ntx    = W / 32;
    const int tile_x = blockIdx.x % ntx;
    const int tile_y = blockIdx.x / ntx;
    const int n      = blockIdx.z;
    const int co_blk = blockIdx.y * 64;

    const int x0  = tile_x * 32;
    const int y0  = tile_y * 8;
    const int xb  = tx * 8;
    const int py  = y0 + ty;
    const int px0 = x0 + xb;
    const int co0 = co_blk + tz * 8;

    float bq[8];
    #pragma unroll
    for (int q = 0; q < 8; q++) bq[q] = bias[co0 + q];

    ull acc[8][4];
    #pragma unroll
    for (int p = 0; p < 8; p++)
        #pragma unroll
        for (int q = 0; q < 4; q++) acc[p][q] = 0ull;

    for (int cc = 0; cc < CIN; cc += 8) {
        __syncthreads();
        // ---- input fill: interior as float4 (640 slots) ----
        for (int s = t; s < 640; s += 256) {
            int row_id = s >> 3, j = s & 7;
            int ci = row_id / 10, r = row_id - ci * 10;
            int gy = y0 + r - 1;
            float4 v = make_float4(0.f, 0.f, 0.f, 0.f);
            if ((unsigned)gy < (unsigned)H)
                v = *(const float4*)&in[((n * CIN + cc + ci) * H + gy) * W + x0 + j * 4];
            *(float4*)&s_in[ci][r][j * 4] = v;
        }
        // ---- input fill: edge columns (160 slots) ----
        if (t < 160) {
            int row_id = t >> 1, side = t & 1;
            int ci = row_id / 10, r = row_id - ci * 10;
            int gy = y0 + r - 1;
            int gx  = side ? (x0 + 32) : (x0 - 1);
            int col = side ? 32 : 34;
            float v = 0.f;
            if ((unsigned)gy < (unsigned)H && (unsigned)gx < (unsigned)W)
                v = in[((n * CIN + cc + ci) * H + gy) * W + gx];
            s_in[ci][r][col] = v;
        }
        // ---- weight fill: float4 (1152 slots), already transposed ----
        for (int s = t; s < 1152; s += 256) {
            int row = s >> 4, j = s & 15;   // row = ci*9+tap
            float4 v = *(const float4*)&wt[(cc * 9 + row) * COUT + co_blk + j * 4];
            *(float4*)&s_w[row * 64 + j * 4] = v;
        }
        __syncthreads();

        #pragma unroll 1
        for (int ci = 0; ci < 8; ci++) {
            #pragma unroll
            for (int dy = 0; dy < 3; dy++) {
                const float* rowp = &s_in[ci][ty + dy][0];
                float4 m0 = *(const float4*)&rowp[xb];
                float4 m1 = *(const float4*)&rowp[xb + 4];
                float wl = rowp[tx == 0 ? 34 : xb - 1];
                float wr = rowp[xb + 8];
                ull d[10];
                d[0] = dup2(wl);
                d[1] = dup2(m0.x); d[2] = dup2(m0.y); d[3] = dup2(m0.z); d[4] = dup2(m0.w);
                d[5] = dup2(m1.x); d[6] = dup2(m1.y); d[7] = dup2(m1.z); d[8] = dup2(m1.w);
                d[9] = dup2(wr);
                #pragma unroll
                for (int dx = 0; dx < 3; dx++) {
                    const ulonglong2* wp =
                        (const ulonglong2*)&s_w[(ci * 9 + dy * 3 + dx) * 64 + tz * 8];
                    ulonglong2 w0 = wp[0], w1 = wp[1];
                    ull wv[4] = {w0.x, w0.y, w1.x, w1.y};
                    #pragma unroll
                    for (int p = 0; p < 8; p++)
                        #pragma unroll
                        for (int q = 0; q < 4; q++)
                            fma2(acc[p][q], d[p + dx], wv[q]);
                }
            }
        }
    }

    // ---- epilogue ----
    int ya = 0, yb2 = 0; float wya = 0.f, wyb = 0.f; int jxb = 0;
    if (FUSE) {
        int jy = py >> 1; bool ev = !(py & 1);
        ya  = ev ? max(jy - 1, 0) : jy;
        yb2 = ev ? jy : min(jy + 1, 63);
        wya = ev ? 0.25f : 0.75f;
        wyb = ev ? 0.75f : 0.25f;
        jxb = (x0 >> 1) + tx * 4 - 1;
    }

    const long obase = (long)(n * COUT) * (H * W) + py * W + px0;
    #pragma unroll
    for (int q2 = 0; q2 < 4; q2++) {
        #pragma unroll
        for (int h = 0; h < 2; h++) {
            int co = co0 + 2 * q2 + h;
            float v[8];
            #pragma unroll
            for (int p = 0; p < 8; p++) {
                float lo, hi;
                unpack2(acc[p][q2], lo, hi);
                float val = (h ? hi : lo) + bq[2 * q2 + h];
                v[p] = (val >= 0.f ? val : 0.2f * val) * 1.41421356237309515f;
            }
            if (FUSE) {
                const float* S = (const float*)g_skip + (n * COUT + co) * 4096;
                float rA[6], rB[6];
                #pragma unroll
                for (int k = 0; k < 6; k++) {
                    int c = min(max(jxb + k, 0), 63);
                    rA[k] = S[ya  * 64 + c];
                    rB[k] = S[yb2 * 64 + c];
                }
                #pragma unroll
                for (int p = 0; p < 8; p++) {
                    int k0 = p >> 1;
                    float sxA, sxB;
                    if ((p & 1) == 0) {
                        sxA = 0.25f * rA[k0] + 0.75f * rA[k0 + 1];
                        sxB = 0.25f * rB[k0] + 0.75f * rB[k0 + 1];
                    } else {
                        sxA = 0.75f * rA[k0 + 1] + 0.25f * rA[k0 + 2];
                        sxB = 0.75f * rB[k0 + 1] + 0.25f * rB[k0 + 2];
                    }
                    float sv = wya * sxA + wyb * sxB;
                    v[p] = (v[p] + sv) * 0.70710678118654752f;
                }
            }
            float* op = out + obase + (long)co * (H * W);
            *(float4*)&op[0] = make_float4(v[0], v[1], v[2], v[3]);
            *(float4*)&op[4] = make_float4(v[4], v[5], v[6], v[7]);
        }
    }
}

// ---------------------------------------------------------------------------
// Bilinear 2x upsample, g_out1 (64) -> g_up1 (128); 4 px per thread.
// ---------------------------------------------------------------------------
__global__ __launch_bounds__(256)
void upsample2x_v3()
{
    int idx = blockIdx.x * 256 + threadIdx.x;         // 8.39M threads
    int oxg = idx & 31;                               // 32 groups of 4 px
    int oy  = (idx >> 5) & 127;
    int nc  = idx >> 12;

    int jy = oy >> 1; bool ev = !(oy & 1);
    int ya  = ev ? max(jy - 1, 0) : jy;
    int yb2 = ev ? jy : min(jy + 1, 63);
    float wya = ev ? 0.25f : 0.75f, wyb = ev ? 0.75f : 0.25f;

    int jxb = oxg * 2 - 1;
    const float* p = (const float*)g_out1 + nc * 4096;
    float rA[4], rB[4];
    #pragma unroll
    for (int k = 0; k < 4; k++) {
        int c = min(max(jxb + k, 0), 63);
        rA[k] = p[ya  * 64 + c];
        rB[k] = p[yb2 * 64 + c];
    }
    float o[4];
    #pragma unroll
    for (int pp = 0; pp < 4; pp++) {
        int k0 = pp >> 1;
        float sxA, sxB;
        if ((pp & 1) == 0) {
            sxA = 0.25f * rA[k0] + 0.75f * rA[k0 + 1];
            sxB = 0.25f * rB[k0] + 0.75f * rB[k0 + 1];
        } else {
            sxA = 0.75f * rA[k0 + 1] + 0.25f * rA[k0 + 2];
            sxB = 0.75f * rB[k0 + 1] + 0.25f * rB[k0 + 2];
        }
        o[pp] = wya * sxA + wyb * sxB;
    }
    *(float4*)&g_up1[(nc * 128 + oy) * 128 + oxg * 4] =
        make_float4(o[0], o[1], o[2], o[3]);
}

// ---------------------------------------------------------------------------
// 1x1 equalized conv at 64-res -> g_skip (weights pre-scaled).
// Tile: 256 px x 64 co. Thread: 8 px (two float4 groups) x 8 co.
// ---------------------------------------------------------------------------
__global__ __launch_bounds__(256)
void skip1x1_v3(const float* __restrict__ x)
{
    __shared__ __align__(16) float s_x[8][260];
    __shared__ __align__(16) float s_w[8 * 64];

    const int t  = threadIdx.x;
    const int tx = t & 31;
    const int tz = t >> 5;
    const int n = blockIdx.z, cob = blockIdx.y * 64, pxb = blockIdx.x * 256;

    ull acc[8][4];
    #pragma unroll
    for (int p = 0; p < 8; p++)
        #pragma unroll
        for (int q = 0; q < 4; q++) acc[p][q] = 0ull;

    for (int cc = 0; cc < 256; cc += 8) {
        __syncthreads();
        for (int s = t; s < 512; s += 256) {      // input: 8ci x 64 float4
            int ci = s >> 6, j = s & 63;
            float4 v = *(const float4*)&x[(n * 256 + cc + ci) * 4096 + pxb + j * 4];
            *(float4*)&s_x[ci][j * 4] = v;
        }
        if (t < 128) {                            // weights: 8ci x 16 float4
            int ci = t >> 4, j = t & 15;
            float4 v = *(const float4*)&g_wskt[(cc + ci) * 128 + cob + j * 4];
            *(float4*)&s_w[ci * 64 + j * 4] = v;
        }
        __syncthreads();
        #pragma unroll 1
        for (int ci = 0; ci < 8; ci++) {
            float4 a0 = *(const float4*)&s_x[ci][tx * 4];
            float4 a1 = *(const float4*)&s_x[ci][128 + tx * 4];
            ull d[8] = {dup2(a0.x), dup2(a0.y), dup2(a0.z), dup2(a0.w),
                        dup2(a1.x), dup2(a1.y), dup2(a1.z), dup2(a1.w)};
            const ulonglong2* wp = (const ulonglong2*)&s_w[ci * 64 + tz * 8];
            ulonglong2 w0 = wp[0], w1 = wp[1];
            ull wv[4] = {w0.x, w0.y, w1.x, w1.y};
            #pragma unroll
            for (int p = 0; p < 8; p++)
                #pragma unroll
                for (int q = 0; q < 4; q++)
                    fma2(acc[p][q], d[p], wv[q]);
        }
    }

    #pragma unroll
    for (int q2 = 0; q2 < 4; q2++) {
        #pragma unroll
        for (int h = 0; h < 2; h++) {
            int co = cob + tz * 8 + 2 * q2 + h;
            float v[8];
            #pragma unroll
            for (int p = 0; p < 8; p++) {
                float lo, hi; unpack2(acc[p][q2], lo, hi);
                v[p] = h ? hi : lo;
            }
            float* op = (float*)g_skip + (n * 128 + co) * 4096 + pxb;
            *(float4*)&op[tx * 4]       = make_float4(v[0], v[1], v[2], v[3]);
            *(float4*)&op[128 + tx * 4] = make_float4(v[4], v[5], v[6], v[7]);
        }
    }
}

// ---------------------------------------------------------------------------
// kernel_launch — kernel launches only (graph-capturable, allocation-free)
// ---------------------------------------------------------------------------
extern "C" void kernel_launch(void* const* d_in, const int* in_sizes, int n_in,
                              void* d_out, int out_size)
{
    const float* x   = (const float*)d_in[0];
    const float* w1  = (const float*)d_in[1];
    const float* b1  = (const float*)d_in[2];
    const float* w2  = (const float*)d_in[3];
    const float* b2  = (const float*)d_in[4];
    const float* wsk = (const float*)d_in[5];
    float* out = (float*)d_out;

    // weight transpose + scale (2304 blocks covers the largest table)
    prep_weights_k<<<2304, 256>>>(w1, w2, wsk);

    // conv1: 3x3 (256->256) @64 -> g_out1.  tiles: 2x8=16, co: 4, n: 8
    conv3x3_v3<64, 64, 256, 256, false><<<dim3(16, 4, 8), 256>>>(x, b1, nullptr);

    // bilinear x2: g_out1 -> g_up1
    upsample2x_v3<<<(8 * 256 * 128 * 128) / (4 * 256), 256>>>();

    // skip 1x1 @64 -> g_skip.  px: 16, co: 2, 8
    skip1x1_v3<<<dim3(16, 2, 8), 256>>>(x);

    // conv2: 3x3 (256->128) @128 + skip fuse -> out.  tiles: 4x16=64, co: 2, n: 8
    conv3x3_v3<128, 128, 256, 128, true><<<dim3(64, 2, 8), 256>>>(nullptr, b2, out);
}

// round 7
// speedup vs baseline: 2.7185x; 1.7267x over previous
#include <cuda_runtime.h>
#include <cuda_bf16.h>
#include <stdint.h>

typedef unsigned long long ull;

// ---------------------------------------------------------------------------
// Scratch (__device__ globals — allocation-free). float4-typed for 16B align.
// ---------------------------------------------------------------------------
__device__ float4 g_x_h [1048576], g_x_l [1048576];   // x  channels-last bf16 split [n][64][64][256]
__device__ float4 g_o1_h[1048576], g_o1_l[1048576];   // conv1 out, same layout
__device__ float4 g_up1_h[4194304], g_up1_l[4194304]; // upsampled, [n][128][128][256]
__device__ float  g_skip[8*128*64*64];                // 1x1 skip at 64-res, NCHW fp32
__device__ float  g_wskt[256*128];                    // skip weights [ci][co], pre-scaled
__device__ float4 g_w1m [147456];  // w1 [tap][chunk16][co256][16hi|16lo] bf16
__device__ float4 g_w2m [73728];   // w2 [tap][chunk16][co128][16hi|16lo] bf16

// ---------------------------------------------------------------------------
// helpers
// ---------------------------------------------------------------------------
__device__ __forceinline__ uint32_t s2u(const void* p) {
    uint32_t a;
    asm("{ .reg .u64 t; cvta.to.shared.u64 t, %1; cvt.u32.u64 %0, t; }" : "=r"(a) : "l"(p));
    return a;
}
__device__ __forceinline__ void bsplit(float v, __nv_bfloat16& h, __nv_bfloat16& l) {
    h = __float2bfloat16(v);
    l = __float2bfloat16(v - __bfloat162float(h));
}
__device__ __forceinline__ void ldsm4(uint32_t r[4], uint32_t a) {
    asm volatile("ldmatrix.sync.aligned.m8n8.x4.shared.b16 {%0,%1,%2,%3}, [%4];"
        : "=r"(r[0]), "=r"(r[1]), "=r"(r[2]), "=r"(r[3]) : "r"(a));
}
__device__ __forceinline__ void ldsm2(uint32_t r[2], uint32_t a) {
    asm volatile("ldmatrix.sync.aligned.m8n8.x2.shared.b16 {%0,%1}, [%2];"
        : "=r"(r[0]), "=r"(r[1]) : "r"(a));
}
__device__ __forceinline__ void mma16816(float c[4], const uint32_t a[4], const uint32_t b[2]) {
    asm volatile("mma.sync.aligned.m16n8k16.row.col.f32.bf16.bf16.f32 "
        "{%0,%1,%2,%3}, {%4,%5,%6,%7}, {%8,%9}, {%0,%1,%2,%3};"
        : "+f"(c[0]), "+f"(c[1]), "+f"(c[2]), "+f"(c[3])
        : "r"(a[0]), "r"(a[1]), "r"(a[2]), "r"(a[3]), "r"(b[0]), "r"(b[1]));
}
__device__ __forceinline__ float lk(float w) { return w >= 0.f ? w : 0.2f * w; }

// FFMA2 helpers (skip1x1 path)
__device__ __forceinline__ void fma2(ull &d, ull a, ull b) {
    asm("fma.rn.f32x2 %0, %1, %2, %0;" : "+l"(d) : "l"(a), "l"(b));
}
__device__ __forceinline__ ull dup2(float v) {
    ull r; asm("mov.b64 %0, {%1, %1};" : "=l"(r) : "f"(v)); return r;
}
__device__ __forceinline__ void unpack2(ull v, float &lo, float &hi) {
    asm("mov.b64 {%0, %1}, %2;" : "=f"(lo), "=f"(hi) : "l"(v));
}

// ---------------------------------------------------------------------------
// prep: weights -> scaled bf16 split, layout [tap][chunk][co][16hi|16lo]
// ---------------------------------------------------------------------------
__global__ __launch_bounds__(256)
void prep_k(const float* __restrict__ w1, const float* __restrict__ w2,
            const float* __restrict__ wsk)
{
    const float SC3 = 1.0f / 48.0f, SC1 = 1.0f / 16.0f;
    int i = blockIdx.x * 256 + threadIdx.x;   // 589824 total
    {   // conv1: 9 x 256co x 256ci
        int tap = i >> 16, r = i & 65535, co = r >> 8, ci = r & 255;
        float v = w1[(co * 256 + ci) * 9 + tap] * SC3;
        __nv_bfloat16 h, l; bsplit(v, h, l);
        long idx = (((long)(tap * 16 + (ci >> 4)) * 256 + co) * 32 + (ci & 15));
        ((__nv_bfloat16*)g_w1m)[idx]      = h;
        ((__nv_bfloat16*)g_w1m)[idx + 16] = l;
    }
    if (i < 294912) {   // conv2: 9 x 128co x 256ci
        int tap = i >> 15, r = i & 32767, co = r >> 8, ci = r & 255;
        float v = w2[(co * 256 + ci) * 9 + tap] * SC3;
        __nv_bfloat16 h, l; bsplit(v, h, l);
        long idx = (((long)(tap * 16 + (ci >> 4)) * 128 + co) * 32 + (ci & 15));
        ((__nv_bfloat16*)g_w2m)[idx]      = h;
        ((__nv_bfloat16*)g_w2m)[idx + 16] = l;
    }
    if (i < 32768) {    // wskt[ci][co]
        int co = i & 127, ci = i >> 7;
        g_wskt[i] = wsk[co * 256 + ci] * SC1;
    }
}

// ---------------------------------------------------------------------------
// convert x: NCHW fp32 -> channels-last bf16 split [n][y][x][256]
// ---------------------------------------------------------------------------
__global__ __launch_bounds__(256)
void convert_x_k(const float* __restrict__ x)
{
    __shared__ float s_t[64 * 129];
    int y = blockIdx.x, n = blockIdx.y, t = threadIdx.x;
    for (int cp = 0; cp < 2; cp++) {
        __syncthreads();
        for (int s = t; s < 8192; s += 256) {
            int ci = s >> 6, xx = s & 63;
            s_t[xx * 129 + ci] = x[((n * 256 + cp * 128 + ci) * 64 + y) * 64 + xx];
        }
        __syncthreads();
        for (int s = t; s < 8192; s += 256) {
            int xx = s >> 7, ci = s & 127;
            __nv_bfloat16 h, l; bsplit(s_t[xx * 129 + ci], h, l);
            long o = ((long)(n * 64 + y) * 64 + xx) * 256 + cp * 128 + ci;
            ((__nv_bfloat16*)g_x_h)[o] = h;
            ((__nv_bfloat16*)g_x_l)[o] = l;
        }
    }
}

// ---------------------------------------------------------------------------
// bilinear 2x upsample of conv1 output (channels-last split in/out)
// ---------------------------------------------------------------------------
__global__ __launch_bounds__(256)
void upsample_k()
{
    int idx = blockIdx.x * 256 + threadIdx.x;   // 524288
    int cg = idx & 3, ox = (idx >> 2) & 127, oy = (idx >> 9) & 127, n = idx >> 16;

    int jy = oy >> 1; bool evy = !(oy & 1);
    int ya = evy ? max(jy - 1, 0) : jy;
    int yb = evy ? jy : min(jy + 1, 63);
    float wya = evy ? 0.25f : 0.75f, wyb = evy ? 0.75f : 0.25f;
    int jx = ox >> 1; bool evx = !(ox & 1);
    int xa = evx ? max(jx - 1, 0) : jx;
    int xb = evx ? jx : min(jx + 1, 63);
    float wxa = evx ? 0.25f : 0.75f, wxb = evx ? 0.75f : 0.25f;

    long b00 = ((long)(n * 64 + ya) * 64 + xa) * 32 + cg * 8;
    long b01 = ((long)(n * 64 + ya) * 64 + xb) * 32 + cg * 8;
    long b10 = ((long)(n * 64 + yb) * 64 + xa) * 32 + cg * 8;
    long b11 = ((long)(n * 64 + yb) * 64 + xb) * 32 + cg * 8;
    long ob  = ((long)(n * 128 + oy) * 128 + ox) * 32 + cg * 8;

    #pragma unroll 2
    for (int j = 0; j < 8; j++) {
        float4 h00 = g_o1_h[b00 + j], l00 = g_o1_l[b00 + j];
        float4 h01 = g_o1_h[b01 + j], l01 = g_o1_l[b01 + j];
        float4 h10 = g_o1_h[b10 + j], l10 = g_o1_l[b10 + j];
        float4 h11 = g_o1_h[b11 + j], l11 = g_o1_l[b11 + j];
        const __nv_bfloat16 *p00h = (const __nv_bfloat16*)&h00, *p00l = (const __nv_bfloat16*)&l00;
        const __nv_bfloat16 *p01h = (const __nv_bfloat16*)&h01, *p01l = (const __nv_bfloat16*)&l01;
        const __nv_bfloat16 *p10h = (const __nv_bfloat16*)&h10, *p10l = (const __nv_bfloat16*)&l10;
        const __nv_bfloat16 *p11h = (const __nv_bfloat16*)&h11, *p11l = (const __nv_bfloat16*)&l11;
        float4 oh4, ol4;
        __nv_bfloat16* qh = (__nv_bfloat16*)&oh4;
        __nv_bfloat16* ql = (__nv_bfloat16*)&ol4;
        #pragma unroll
        for (int c = 0; c < 8; c++) {
            float v00 = __bfloat162float(p00h[c]) + __bfloat162float(p00l[c]);
            float v01 = __bfloat162float(p01h[c]) + __bfloat162float(p01l[c]);
            float v10 = __bfloat162float(p10h[c]) + __bfloat162float(p10l[c]);
            float v11 = __bfloat162float(p11h[c]) + __bfloat162float(p11l[c]);
            float v = wya * (wxa * v00 + wxb * v01) + wyb * (wxa * v10 + wxb * v11);
            __nv_bfloat16 h, l; bsplit(v, h, l);
            qh[c] = h; ql[c] = l;
        }
        g_up1_h[ob + j] = oh4;
        g_up1_l[ob + j] = ol4;
    }
}

// ---------------------------------------------------------------------------
// 1x1 skip conv at 64-res (FFMA2 path)
// ---------------------------------------------------------------------------
__global__ __launch_bounds__(256)
void skip1x1_v3(const float* __restrict__ x)
{
    __shared__ __align__(16) float s_x[8][260];
    __shared__ __align__(16) float s_w[8 * 64];

    const int t  = threadIdx.x;
    const int tx = t & 31;
    const int tz = t >> 5;
    const int n = blockIdx.z, cob = blockIdx.y * 64, pxb = blockIdx.x * 256;

    ull acc[8][4];
    #pragma unroll
    for (int p = 0; p < 8; p++)
        #pragma unroll
        for (int q = 0; q < 4; q++) acc[p][q] = 0ull;

    for (int cc = 0; cc < 256; cc += 8) {
        __syncthreads();
        for (int s = t; s < 512; s += 256) {
            int ci = s >> 6, j = s & 63;
            float4 v = *(const float4*)&x[(n * 256 + cc + ci) * 4096 + pxb + j * 4];
            *(float4*)&s_x[ci][j * 4] = v;
        }
        if (t < 128) {
            int ci = t >> 4, j = t & 15;
            float4 v = *(const float4*)&g_wskt[(cc + ci) * 128 + cob + j * 4];
            *(float4*)&s_w[ci * 64 + j * 4] = v;
        }
        __syncthreads();
        #pragma unroll 1
        for (int ci = 0; ci < 8; ci++) {
            float4 a0 = *(const float4*)&s_x[ci][tx * 4];
            float4 a1 = *(const float4*)&s_x[ci][128 + tx * 4];
            ull d[8] = {dup2(a0.x), dup2(a0.y), dup2(a0.z), dup2(a0.w),
                        dup2(a1.x), dup2(a1.y), dup2(a1.z), dup2(a1.w)};
            const ulonglong2* wp = (const ulonglong2*)&s_w[ci * 64 + tz * 8];
            ulonglong2 w0 = wp[0], w1 = wp[1];
            ull wv[4] = {w0.x, w0.y, w1.x, w1.y};
            #pragma unroll
            for (int p = 0; p < 8; p++)
                #pragma unroll
                for (int q = 0; q < 4; q++)
                    fma2(acc[p][q], d[p], wv[q]);
        }
    }
    #pragma unroll
    for (int q2 = 0; q2 < 4; q2++) {
        #pragma unroll
        for (int h = 0; h < 2; h++) {
            int co = cob + tz * 8 + 2 * q2 + h;
            float v[8];
            #pragma unroll
            for (int p = 0; p < 8; p++) {
                float lo, hi; unpack2(acc[p][q2], lo, hi);
                v[p] = h ? hi : lo;
            }
            float* op = (float*)g_skip + (n * 128 + co) * 4096 + pxb;
            *(float4*)&op[tx * 4]       = make_float4(v[0], v[1], v[2], v[3]);
            *(float4*)&op[128 + tx * 4] = make_float4(v[4], v[5], v[6], v[7]);
        }
    }
}

// ---------------------------------------------------------------------------
// Tensor-core 3x3 conv via mma.sync m16n8k16 bf16 (bf16x3 split).
// Block: 64 co x 128 px (CONV=1: 2 rows of 64; CONV=2: 1 row of 128).
// Warp tile 32co x 32px; 8 warps (2 co-groups x 4 px-groups).
// ---------------------------------------------------------------------------
template<int CONV>
__global__ __launch_bounds__(256)
void convmma_k(const float* __restrict__ bias, float* __restrict__ out)
{
    constexpr int HW   = (CONV == 1) ? 64 : 128;
    constexpr int NCO  = (CONV == 1) ? 256 : 128;
    constexpr int ROWS = (CONV == 1) ? 2 : 1;
    constexpr int NROW = ROWS + 2;
    constexpr int NPX  = HW + 2;
    constexpr int PXSH = (CONV == 1) ? 6 : 7;

    __shared__ __align__(16) char sA[3 * 64 * 80];        // 3 taps x [co][16hi|16lo], 80B stride
    __shared__ __align__(16) char sB[NROW * NPX * 80];    // [row][px][16hi|16lo], 80B stride

    const int t = threadIdx.x, wid = t >> 5, lane = t & 31;
    const int warp_co = (wid >> 2) * 32;
    const int warp_px = (wid & 3) * 32;
    const int y0    = blockIdx.x * ROWS;
    const int coblk = blockIdx.y;
    const int n     = blockIdx.z;

    const float4* aH = (CONV == 1) ? g_x_h : g_up1_h;
    const float4* aL = (CONV == 1) ? g_x_l : g_up1_l;
    const float4* wM = (CONV == 1) ? g_w1m : g_w2m;

    const uint32_t sAu = s2u(sA), sBu = s2u(sB);

    // per-lane ldmatrix address components
    const uint32_t aoff = sAu + (uint32_t)((warp_co + (lane & 15)) * 80 + ((lane >> 4) & 1) * 16);
    uint32_t boff[4];
    #pragma unroll
    for (int nt = 0; nt < 4; nt++) {
        int px = warp_px + nt * 8 + (lane & 7);
        int x = px & (HW - 1), r = px >> PXSH;
        boff[nt] = sBu + (uint32_t)((r * NPX + x + 1) * 80 + ((lane >> 3) & 1) * 16);
    }

    float acc[2][4][4];
    #pragma unroll
    for (int m = 0; m < 2; m++)
        #pragma unroll
        for (int nt = 0; nt < 4; nt++)
            #pragma unroll
            for (int q = 0; q < 4; q++) acc[m][nt][q] = 0.f;

    for (int chunk = 0; chunk < 16; chunk++) {
        __syncthreads();
        // ---- load B: NROW rows x NPX px, hi+lo 32B each ----
        constexpr int NSLOT = NROW * NPX * 2;
        for (int s = t; s < NSLOT; s += 256) {
            int lohi = s & 1, ps = s >> 1;
            int px = ps % NPX, row = ps / NPX;
            int gy = y0 + row - 1, gx = px - 1;
            float4 v0 = make_float4(0.f, 0.f, 0.f, 0.f), v1 = v0;
            if ((unsigned)gy < (unsigned)HW && (unsigned)gx < (unsigned)HW) {
                const float4* src = (lohi ? aL : aH)
                    + ((long)(n * HW + gy) * HW + gx) * 32 + chunk * 2;
                v0 = src[0]; v1 = src[1];
            }
            float4* d = (float4*)(sB + ps * 80 + lohi * 32);
            d[0] = v0; d[1] = v1;
        }
        for (int dyg = 0; dyg < 3; dyg++) {
            if (dyg) __syncthreads();
            // ---- load A: 3 taps (dyg*3 .. +2), 64 co x 64B each ----
            for (int s = t; s < 768; s += 256) {
                int seg = s >> 8, r2 = s & 255, co_l = r2 >> 2, part = r2 & 3;
                int tap = dyg * 3 + seg;
                float4 v = wM[(((long)(tap * 16 + chunk)) * NCO + coblk * 64 + co_l) * 4 + part];
                *(float4*)(sA + seg * 5120 + co_l * 80 + part * 16) = v;
            }
            __syncthreads();
            #pragma unroll
            for (int dx = 0; dx < 3; dx++) {
                uint32_t ah[2][4], al[2][4];
                #pragma unroll
                for (int m = 0; m < 2; m++) {
                    ldsm4(ah[m], aoff + dx * 5120 + m * 1280);
                    ldsm4(al[m], aoff + dx * 5120 + m * 1280 + 32);
                }
                uint32_t bshift = (uint32_t)((dyg * NPX + dx - 1) * 80);
                uint32_t bh[4][2], bl[4][2];
                #pragma unroll
                for (int nt = 0; nt < 4; nt++) {
                    ldsm2(bh[nt], boff[nt] + bshift);
                    ldsm2(bl[nt], boff[nt] + bshift + 32);
                }
                // 3 passes, acc reused every 8 mma (break RAW chains)
                #pragma unroll
                for (int m = 0; m < 2; m++)
                    #pragma unroll
                    for (int nt = 0; nt < 4; nt++) mma16816(acc[m][nt], ah[m], bh[nt]);
                #pragma unroll
                for (int m = 0; m < 2; m++)
                    #pragma unroll
                    for (int nt = 0; nt < 4; nt++) mma16816(acc[m][nt], ah[m], bl[nt]);
                #pragma unroll
                for (int m = 0; m < 2; m++)
                    #pragma unroll
                    for (int nt = 0; nt < 4; nt++) mma16816(acc[m][nt], al[m], bh[nt]);
            }
        }
    }

    // ---- epilogue ----
    const int gid = lane >> 2, t2 = lane & 3;
    #pragma unroll
    for (int m = 0; m < 2; m++) {
        int co0 = coblk * 64 + warp_co + m * 16 + gid;
        float b0 = bias[co0], b1 = bias[co0 + 8];
        #pragma unroll
        for (int nt = 0; nt < 4; nt++) {
            int px = warp_px + nt * 8 + 2 * t2;
            float v00 = lk(acc[m][nt][0] + b0), v01 = lk(acc[m][nt][1] + b0);
            float v10 = lk(acc[m][nt][2] + b1), v11 = lk(acc[m][nt][3] + b1);
            if (CONV == 2) {
                // store leaky(v+b); skipadd_k later adds skip*2^-0.5 (sqrt2/sqrt2 = 1)
                long o0 = ((long)(n * 128 + co0) * 128 + y0) * 128 + px;
                long o1 = ((long)(n * 128 + co0 + 8) * 128 + y0) * 128 + px;
                *(float2*)&out[o0] = make_float2(v00, v01);
                *(float2*)&out[o1] = make_float2(v10, v11);
            } else {
                int y = y0 + (px >> 6), x = px & 63;
                const float S2 = 1.41421356237309515f;
                float vv[4] = {v00 * S2, v01 * S2, v10 * S2, v11 * S2};
                int cc2[4]  = {co0, co0, co0 + 8, co0 + 8};
                int xx2[4]  = {x, x + 1, x, x + 1};
                #pragma unroll
                for (int q = 0; q < 4; q++) {
                    __nv_bfloat16 h, l; bsplit(vv[q], h, l);
                    long o = ((long)(n * 64 + y) * 64 + xx2[q]) * 256 + cc2[q];
                    ((__nv_bfloat16*)g_o1_h)[o] = h;
                    ((__nv_bfloat16*)g_o1_l)[o] = l;
                }
            }
        }
    }
}

// ---------------------------------------------------------------------------
// final: out += upsampled-skip * (1/sqrt(2))
// ---------------------------------------------------------------------------
__global__ __launch_bounds__(256)
void skipadd_k(float* __restrict__ out)
{
    int idx = blockIdx.x * 256 + threadIdx.x;   // 4,194,304
    int xg = idx & 31, y = (idx >> 5) & 127, co = (idx >> 12) & 127, n = idx >> 19;

    int jy = y >> 1; bool ev = !(y & 1);
    int ya = ev ? max(jy - 1, 0) : jy;
    int yb = ev ? jy : min(jy + 1, 63);
    float wya = ev ? 0.25f : 0.75f, wyb = ev ? 0.75f : 0.25f;

    const float* S = g_skip + (long)(n * 128 + co) * 4096;
    int jxb = xg * 2 - 1;
    float rA[4], rB[4];
    #pragma unroll
    for (int k = 0; k < 4; k++) {
        int c = min(max(jxb + k, 0), 63);
        rA[k] = S[ya * 64 + c];
        rB[k] = S[yb * 64 + c];
    }
    long o = (((long)(n * 128 + co) * 128 + y) * 128 + xg * 4);
    float4 v = *(float4*)&out[o];
    float* ov = &v.x;
    #pragma unroll
    for (int p = 0; p < 4; p++) {
        int k0 = p >> 1;
        float sxA, sxB;
        if ((p & 1) == 0) {
            sxA = 0.25f * rA[k0] + 0.75f * rA[k0 + 1];
            sxB = 0.25f * rB[k0] + 0.75f * rB[k0 + 1];
        } else {
            sxA = 0.75f * rA[k0 + 1] + 0.25f * rA[k0 + 2];
            sxB = 0.75f * rB[k0 + 1] + 0.25f * rB[k0 + 2];
        }
        ov[p] += (wya * sxA + wyb * sxB) * 0.70710678118654752f;
    }
    *(float4*)&out[o] = v;
}

// ---------------------------------------------------------------------------
// kernel_launch — kernel launches only (graph-capturable, allocation-free)
// ---------------------------------------------------------------------------
extern "C" void kernel_launch(void* const* d_in, const int* in_sizes, int n_in,
                              void* d_out, int out_size)
{
    const float* x   = (const float*)d_in[0];
    const float* w1  = (const float*)d_in[1];
    const float* b1  = (const float*)d_in[2];
    const float* w2  = (const float*)d_in[3];
    const float* b2  = (const float*)d_in[4];
    const float* wsk = (const float*)d_in[5];
    float* out = (float*)d_out;

    prep_k<<<2304, 256>>>(w1, w2, wsk);
    convert_x_k<<<dim3(64, 8), 256>>>(x);
    skip1x1_v3<<<dim3(16, 2, 8), 256>>>(x);
    convmma_k<1><<<dim3(32, 4, 8), 256>>>(b1, nullptr);
    upsample_k<<<2048, 256>>>();
    convmma_k<2><<<dim3(128, 2, 8), 256>>>(b2, out);
    skipadd_k<<<16384, 256>>>(out);
}

// round 11
// speedup vs baseline: 3.6137x; 1.3293x over previous
#include <cuda_runtime.h>
#include <cuda_bf16.h>
#include <stdint.h>
#include <string.h>

typedef unsigned long long ull;

// ---------------------------------------------------------------------------
// Scratch (__device__ globals — allocation-free)
// ---------------------------------------------------------------------------
__device__ float4 g_x_h [1048576], g_x_l [1048576];   // x  channels-last bf16 split [n][64][64][256]
__device__ float4 g_o1_h[1048576], g_o1_l[1048576];   // conv1 out, same layout
__device__ float4 g_up1_h[4194304], g_up1_l[4194304]; // upsampled, [n][128][128][256]
__device__ float  g_skip[8*128*64*64];                // 1x1 skip at 64-res, NCHW fp32
__device__ float  g_wskt[256*128];                    // skip weights [ci][co], pre-scaled
// Weights in mma.sync A-fragment layout: [ (tap*16+chunk)*MT + mt ][lane] -> {hi uint4, lo uint4}
__device__ uint4  g_w1f[147456];   // conv1: 144 * 16 mtiles * 32 lanes * 2
__device__ uint4  g_w2f[73728];    // conv2: 144 *  8 mtiles * 32 lanes * 2

// ---------------------------------------------------------------------------
// helpers
// ---------------------------------------------------------------------------
__device__ __forceinline__ uint32_t s2u(const void* p) {
    uint32_t a;
    asm("{ .reg .u64 t; cvta.to.shared.u64 t, %1; cvt.u32.u64 %0, t; }" : "=r"(a) : "l"(p));
    return a;
}
__device__ __forceinline__ void bsplit(float v, __nv_bfloat16& h, __nv_bfloat16& l) {
    h = __float2bfloat16(v);
    l = __float2bfloat16(v - __bfloat162float(h));
}
__device__ __forceinline__ unsigned short wsplitbits(float v, int hl) {
    __nv_bfloat16 h = __float2bfloat16(v);
    __nv_bfloat16 r = h;
    if (hl) r = __float2bfloat16(v - __bfloat162float(h));
    unsigned short us; memcpy(&us, &r, 2);
    return us;
}
__device__ __forceinline__ void ldsm4(uint32_t r[4], uint32_t a) {
    asm volatile("ldmatrix.sync.aligned.m8n8.x4.shared.b16 {%0,%1,%2,%3}, [%4];"
        : "=r"(r[0]), "=r"(r[1]), "=r"(r[2]), "=r"(r[3]) : "r"(a));
}
__device__ __forceinline__ void mma16816(float c[4], const uint32_t a[4], const uint32_t b[2]) {
    asm volatile("mma.sync.aligned.m16n8k16.row.col.f32.bf16.bf16.f32 "
        "{%0,%1,%2,%3}, {%4,%5,%6,%7}, {%8,%9}, {%0,%1,%2,%3};"
        : "+f"(c[0]), "+f"(c[1]), "+f"(c[2]), "+f"(c[3])
        : "r"(a[0]), "r"(a[1]), "r"(a[2]), "r"(a[3]), "r"(b[0]), "r"(b[1]));
}
__device__ __forceinline__ float lk(float w) { return w >= 0.f ? w : 0.2f * w; }

__device__ __forceinline__ void cpasync16(uint32_t dst, const void* src, int ok) {
    uint64_t gp; asm("cvta.to.global.u64 %0, %1;" : "=l"(gp) : "l"(src));
    asm volatile("cp.async.cg.shared.global [%0], [%1], 16, %2;"
        :: "r"(dst), "l"(gp), "r"(ok ? 16 : 0) : "memory");
}

// FFMA2 helpers (skip1x1 path)
__device__ __forceinline__ void fma2(ull &d, ull a, ull b) {
    asm("fma.rn.f32x2 %0, %1, %2, %0;" : "+l"(d) : "l"(a), "l"(b));
}
__device__ __forceinline__ ull dup2(float v) {
    ull r; asm("mov.b64 %0, {%1, %1};" : "=l"(r) : "f"(v)); return r;
}
__device__ __forceinline__ void unpack2(ull v, float &lo, float &hi) {
    asm("mov.b64 {%0, %1}, %2;" : "=f"(lo), "=f"(hi) : "l"(v));
}

// ---------------------------------------------------------------------------
// prep: weights -> scaled bf16 split in mma A-fragment layout + skip weights
// fragment mapping (m16n8k16, A row-major): lane l holds
//   a0 = W[r0][c0,c0+1], a1 = W[r0+8][c0,c0+1], a2 = W[r0][c0+8,+9], a3 = W[r0+8][c0+8,+9]
//   r0 = l>>2 (within 16-row mtile), c0 = 2*(l&3) (within 16-ci chunk)
// ---------------------------------------------------------------------------
__global__ __launch_bounds__(256)
void prep_k(const float* __restrict__ w1, const float* __restrict__ w2,
            const float* __restrict__ wsk)
{
    const float SC3 = 1.0f / 48.0f, SC1 = 1.0f / 16.0f;
    int i = blockIdx.x * 256 + threadIdx.x;   // 262144 threads
    if (i < 147456) {   // conv1: MT=16
        int hl = i & 1, lane = (i >> 1) & 31, mt = (i >> 6) & 15, tc = i >> 10;
        int tap = tc >> 4, chunk = tc & 15;
        int r0 = lane >> 2, c0 = 2 * (lane & 3), cib = chunk * 16;
        int co0 = mt * 16 + r0, co1 = co0 + 8;
        uint4 v;
        v.x = (uint32_t)wsplitbits(w1[(co0*256 + cib+c0  )*9 + tap]*SC3, hl)
            | ((uint32_t)wsplitbits(w1[(co0*256 + cib+c0+1)*9 + tap]*SC3, hl) << 16);
        v.y = (uint32_t)wsplitbits(w1[(co1*256 + cib+c0  )*9 + tap]*SC3, hl)
            | ((uint32_t)wsplitbits(w1[(co1*256 + cib+c0+1)*9 + tap]*SC3, hl) << 16);
        v.z = (uint32_t)wsplitbits(w1[(co0*256 + cib+c0+8)*9 + tap]*SC3, hl)
            | ((uint32_t)wsplitbits(w1[(co0*256 + cib+c0+9)*9 + tap]*SC3, hl) << 16);
        v.w = (uint32_t)wsplitbits(w1[(co1*256 + cib+c0+8)*9 + tap]*SC3, hl)
            | ((uint32_t)wsplitbits(w1[(co1*256 + cib+c0+9)*9 + tap]*SC3, hl) << 16);
        g_w1f[i] = v;
    }
    if (i < 73728) {    // conv2: MT=8
        int hl = i & 1, lane = (i >> 1) & 31, mt = (i >> 6) & 7, tc = i >> 9;
        int tap = tc >> 4, chunk = tc & 15;
        int r0 = lane >> 2, c0 = 2 * (lane & 3), cib = chunk * 16;
        int co0 = mt * 16 + r0, co1 = co0 + 8;
        uint4 v;
        v.x = (uint32_t)wsplitbits(w2[(co0*256 + cib+c0  )*9 + tap]*SC3, hl)
            | ((uint32_t)wsplitbits(w2[(co0*256 + cib+c0+1)*9 + tap]*SC3, hl) << 16);
        v.y = (uint32_t)wsplitbits(w2[(co1*256 + cib+c0  )*9 + tap]*SC3, hl)
            | ((uint32_t)wsplitbits(w2[(co1*256 + cib+c0+1)*9 + tap]*SC3, hl) << 16);
        v.z = (uint32_t)wsplitbits(w2[(co0*256 + cib+c0+8)*9 + tap]*SC3, hl)
            | ((uint32_t)wsplitbits(w2[(co0*256 + cib+c0+9)*9 + tap]*SC3, hl) << 16);
        v.w = (uint32_t)wsplitbits(w2[(co1*256 + cib+c0+8)*9 + tap]*SC3, hl)
            | ((uint32_t)wsplitbits(w2[(co1*256 + cib+c0+9)*9 + tap]*SC3, hl) << 16);
        g_w2f[i] = v;
    }
    if (i < 32768) {    // wskt[ci][co]
        int co = i & 127, ci = i >> 7;
        g_wskt[i] = wsk[co * 256 + ci] * SC1;
    }
}

// ---------------------------------------------------------------------------
// convert x: NCHW fp32 -> channels-last bf16 split [n][y][x][256]
// ---------------------------------------------------------------------------
__global__ __launch_bounds__(256)
void convert_x_k(const float* __restrict__ x)
{
    __shared__ float s_t[64 * 129];
    int y = blockIdx.x, n = blockIdx.y, t = threadIdx.x;
    for (int cp = 0; cp < 2; cp++) {
        __syncthreads();
        for (int s = t; s < 8192; s += 256) {
            int ci = s >> 6, xx = s & 63;
            s_t[xx * 129 + ci] = x[((n * 256 + cp * 128 + ci) * 64 + y) * 64 + xx];
        }
        __syncthreads();
        for (int s = t; s < 8192; s += 256) {
            int xx = s >> 7, ci = s & 127;
            __nv_bfloat16 h, l; bsplit(s_t[xx * 129 + ci], h, l);
            long o = ((long)(n * 64 + y) * 64 + xx) * 256 + cp * 128 + ci;
            ((__nv_bfloat16*)g_x_h)[o] = h;
            ((__nv_bfloat16*)g_x_l)[o] = l;
        }
    }
}

// ---------------------------------------------------------------------------
// bilinear 2x upsample of conv1 output (channels-last split in/out)
// ---------------------------------------------------------------------------
__global__ __launch_bounds__(256)
void upsample_k()
{
    int idx = blockIdx.x * 256 + threadIdx.x;   // 524288
    int cg = idx & 3, ox = (idx >> 2) & 127, oy = (idx >> 9) & 127, n = idx >> 16;

    int jy = oy >> 1; bool evy = !(oy & 1);
    int ya = evy ? max(jy - 1, 0) : jy;
    int yb = evy ? jy : min(jy + 1, 63);
    float wya = evy ? 0.25f : 0.75f, wyb = evy ? 0.75f : 0.25f;
    int jx = ox >> 1; bool evx = !(ox & 1);
    int xa = evx ? max(jx - 1, 0) : jx;
    int xb = evx ? jx : min(jx + 1, 63);
    float wxa = evx ? 0.25f : 0.75f, wxb = evx ? 0.75f : 0.25f;

    long b00 = ((long)(n * 64 + ya) * 64 + xa) * 32 + cg * 8;
    long b01 = ((long)(n * 64 + ya) * 64 + xb) * 32 + cg * 8;
    long b10 = ((long)(n * 64 + yb) * 64 + xa) * 32 + cg * 8;
    long b11 = ((long)(n * 64 + yb) * 64 + xb) * 32 + cg * 8;
    long ob  = ((long)(n * 128 + oy) * 128 + ox) * 32 + cg * 8;

    #pragma unroll 2
    for (int j = 0; j < 8; j++) {
        float4 h00 = g_o1_h[b00 + j], l00 = g_o1_l[b00 + j];
        float4 h01 = g_o1_h[b01 + j], l01 = g_o1_l[b01 + j];
        float4 h10 = g_o1_h[b10 + j], l10 = g_o1_l[b10 + j];
        float4 h11 = g_o1_h[b11 + j], l11 = g_o1_l[b11 + j];
        const __nv_bfloat16 *p00h = (const __nv_bfloat16*)&h00, *p00l = (const __nv_bfloat16*)&l00;
        const __nv_bfloat16 *p01h = (const __nv_bfloat16*)&h01, *p01l = (const __nv_bfloat16*)&l01;
        const __nv_bfloat16 *p10h = (const __nv_bfloat16*)&h10, *p10l = (const __nv_bfloat16*)&l10;
        const __nv_bfloat16 *p11h = (const __nv_bfloat16*)&h11, *p11l = (const __nv_bfloat16*)&l11;
        float4 oh4, ol4;
        __nv_bfloat16* qh = (__nv_bfloat16*)&oh4;
        __nv_bfloat16* ql = (__nv_bfloat16*)&ol4;
        #pragma unroll
        for (int c = 0; c < 8; c++) {
            float v00 = __bfloat162float(p00h[c]) + __bfloat162float(p00l[c]);
            float v01 = __bfloat162float(p01h[c]) + __bfloat162float(p01l[c]);
            float v10 = __bfloat162float(p10h[c]) + __bfloat162float(p10l[c]);
            float v11 = __bfloat162float(p11h[c]) + __bfloat162float(p11l[c]);
            float v = wya * (wxa * v00 + wxb * v01) + wyb * (wxa * v10 + wxb * v11);
            __nv_bfloat16 h, l; bsplit(v, h, l);
            qh[c] = h; ql[c] = l;
        }
        g_up1_h[ob + j] = oh4;
        g_up1_l[ob + j] = ol4;
    }
}

// ---------------------------------------------------------------------------
// 1x1 skip conv at 64-res (FFMA2 path)
// ---------------------------------------------------------------------------
__global__ __launch_bounds__(256)
void skip1x1_v3(const float* __restrict__ x)
{
    __shared__ __align__(16) float s_x[8][260];
    __shared__ __align__(16) float s_w[8 * 64];

    const int t  = threadIdx.x;
    const int tx = t & 31;
    const int tz = t >> 5;
    const int n = blockIdx.z, cob = blockIdx.y * 64, pxb = blockIdx.x * 256;

    ull acc[8][4];
    #pragma unroll
    for (int p = 0; p < 8; p++)
        #pragma unroll
        for (int q = 0; q < 4; q++) acc[p][q] = 0ull;

    for (int cc = 0; cc < 256; cc += 8) {
        __syncthreads();
        for (int s = t; s < 512; s += 256) {
            int ci = s >> 6, j = s & 63;
            float4 v = *(const float4*)&x[(n * 256 + cc + ci) * 4096 + pxb + j * 4];
            *(float4*)&s_x[ci][j * 4] = v;
        }
        if (t < 128) {
            int ci = t >> 4, j = t & 15;
            float4 v = *(const float4*)&g_wskt[(cc + ci) * 128 + cob + j * 4];
            *(float4*)&s_w[ci * 64 + j * 4] = v;
        }
        __syncthreads();
        #pragma unroll 1
        for (int ci = 0; ci < 8; ci++) {
            float4 a0 = *(const float4*)&s_x[ci][tx * 4];
            float4 a1 = *(const float4*)&s_x[ci][128 + tx * 4];
            ull d[8] = {dup2(a0.x), dup2(a0.y), dup2(a0.z), dup2(a0.w),
                        dup2(a1.x), dup2(a1.y), dup2(a1.z), dup2(a1.w)};
            const ulonglong2* wp = (const ulonglong2*)&s_w[ci * 64 + tz * 8];
            ulonglong2 w0 = wp[0], w1 = wp[1];
            ull wv[4] = {w0.x, w0.y, w1.x, w1.y};
            #pragma unroll
            for (int p = 0; p < 8; p++)
                #pragma unroll
                for (int q = 0; q < 4; q++)
                    fma2(acc[p][q], d[p], wv[q]);
        }
    }
    #pragma unroll
    for (int q2 = 0; q2 < 4; q2++) {
        #pragma unroll
        for (int h = 0; h < 2; h++) {
            int co = cob + tz * 8 + 2 * q2 + h;
            float v[8];
            #pragma unroll
            for (int p = 0; p < 8; p++) {
                float lo, hi; unpack2(acc[p][q2], lo, hi);
                v[p] = h ? hi : lo;
            }
            float* op = (float*)g_skip + (n * 128 + co) * 4096 + pxb;
            *(float4*)&op[tx * 4]       = make_float4(v[0], v[1], v[2], v[3]);
            *(float4*)&op[128 + tx * 4] = make_float4(v[4], v[5], v[6], v[7]);
        }
    }
}

// ---------------------------------------------------------------------------
// Tensor-core 3x3 conv via mma.sync m16n8k16 bf16 (bf16x3 split).
// A fragments loaded directly from global (pre-packed), B via cp.async + ldsm4.
// Block: 64 co x 128 px. Warp tile 32co x 32px.
// ---------------------------------------------------------------------------
template<int CONV>
__global__ __launch_bounds__(256)
void convmma_k(const float* __restrict__ bias, float* __restrict__ out)
{
    constexpr int HW   = (CONV == 1) ? 64 : 128;
    constexpr int MT   = (CONV == 1) ? 16 : 8;
    constexpr int ROWS = (CONV == 1) ? 2 : 1;
    constexpr int NROW = ROWS + 2;
    constexpr int NPX  = HW + 2;
    constexpr int PXSH = (CONV == 1) ? 6 : 7;
    constexpr int U    = NROW * NPX * 4;     // 16B cp.async units per chunk

    __shared__ __align__(16) char sB[NROW * NPX * 80];

    const int t = threadIdx.x, wid = t >> 5, lane = t & 31;
    const int warp_co = (wid >> 2) * 32;
    const int warp_px = (wid & 3) * 32;
    const int y0    = blockIdx.x * ROWS;
    const int coblk = blockIdx.y;
    const int n     = blockIdx.z;

    const float4* aH = (CONV == 1) ? g_x_h : g_up1_h;
    const float4* aL = (CONV == 1) ? g_x_l : g_up1_l;
    const uint4*  wf = (CONV == 1) ? g_w1f : g_w2f;
    const int mt0 = coblk * 4 + (warp_co >> 4);

    const uint32_t sBu = s2u(sB);

    // ldsm4 address per nt-pair j: lanes 0-7: nt=2j k0-7; 8-15: nt=2j k8-15;
    //                              16-23: nt=2j+1 k0-7; 24-31: nt=2j+1 k8-15
    uint32_t boff2[2];
    #pragma unroll
    for (int j = 0; j < 2; j++) {
        int ntl = j * 2 + ((lane >> 4) & 1);
        int px = warp_px + ntl * 8 + (lane & 7);
        int x = px & (HW - 1), r = px >> PXSH;
        boff2[j] = sBu + (uint32_t)((r * NPX + x + 1) * 80 + ((lane >> 3) & 1) * 16);
    }

    float acc[2][4][4];
    #pragma unroll
    for (int m = 0; m < 2; m++)
        #pragma unroll
        for (int nt = 0; nt < 4; nt++)
            #pragma unroll
            for (int q = 0; q < 4; q++) acc[m][nt][q] = 0.f;

    for (int chunk = 0; chunk < 16; chunk++) {
        __syncthreads();
        // ---- B fill via cp.async (zfill halo) ----
        for (int s = t; s < U; s += 256) {
            int sub = s & 1, lohi = (s >> 1) & 1, ps = s >> 2;
            int px = ps % NPX, row = ps / NPX;
            int gy = y0 + row - 1, gx = px - 1;
            int ok = ((unsigned)gy < (unsigned)HW) & ((unsigned)gx < (unsigned)HW);
            int cy = ok ? gy : 0, cx = ok ? gx : 0;
            const float4* sp = (lohi ? aL : aH)
                + ((long)(n * HW + cy) * HW + cx) * 32 + chunk * 2 + sub;
            cpasync16(sBu + (uint32_t)(ps * 80 + lohi * 32 + sub * 16), sp, ok);
        }
        asm volatile("cp.async.commit_group;" ::: "memory");
        asm volatile("cp.async.wait_group 0;" ::: "memory");
        __syncthreads();

        #pragma unroll
        for (int dyg = 0; dyg < 3; dyg++) {
            #pragma unroll
            for (int dx = 0; dx < 3; dx++) {
                const int tap = dyg * 3 + dx;
                // A fragments: direct LDG.128 (L1-resident, shared across px-warps)
                long fb = (((long)(tap * 16 + chunk) * MT + mt0) * 32 + lane) * 2;
                uint4 ah0 = __ldg(&wf[fb]);
                uint4 al0 = __ldg(&wf[fb + 1]);
                uint4 ah1 = __ldg(&wf[fb + 64]);
                uint4 al1 = __ldg(&wf[fb + 65]);
                // B fragments via ldsm4 (2 n-frags per instruction)
                int bshift = (dyg * NPX + dx - 1) * 80;
                uint32_t bh[4][2], bl[4][2];
                #pragma unroll
                for (int j = 0; j < 2; j++) {
                    uint32_t rj[4];
                    ldsm4(rj, boff2[j] + bshift);
                    bh[2*j][0] = rj[0]; bh[2*j][1] = rj[1];
                    bh[2*j+1][0] = rj[2]; bh[2*j+1][1] = rj[3];
                    ldsm4(rj, boff2[j] + bshift + 32);
                    bl[2*j][0] = rj[0]; bl[2*j][1] = rj[1];
                    bl[2*j+1][0] = rj[2]; bl[2*j+1][1] = rj[3];
                }
                const uint32_t* ah[2] = {(const uint32_t*)&ah0, (const uint32_t*)&ah1};
                const uint32_t* al[2] = {(const uint32_t*)&al0, (const uint32_t*)&al1};
                #pragma unroll
                for (int m = 0; m < 2; m++)
                    #pragma unroll
                    for (int nt = 0; nt < 4; nt++) mma16816(acc[m][nt], ah[m], bh[nt]);
                #pragma unroll
                for (int m = 0; m < 2; m++)
                    #pragma unroll
                    for (int nt = 0; nt < 4; nt++) mma16816(acc[m][nt], ah[m], bl[nt]);
                #pragma unroll
                for (int m = 0; m < 2; m++)
                    #pragma unroll
                    for (int nt = 0; nt < 4; nt++) mma16816(acc[m][nt], al[m], bh[nt]);
            }
        }
    }

    // ---- epilogue ----
    const int gid = lane >> 2, t2 = lane & 3;
    #pragma unroll
    for (int m = 0; m < 2; m++) {
        int co0 = coblk * 64 + warp_co + m * 16 + gid;
        float b0 = bias[co0], b1 = bias[co0 + 8];
        #pragma unroll
        for (int nt = 0; nt < 4; nt++) {
            int px = warp_px + nt * 8 + 2 * t2;
            float v00 = lk(acc[m][nt][0] + b0), v01 = lk(acc[m][nt][1] + b0);
            float v10 = lk(acc[m][nt][2] + b1), v11 = lk(acc[m][nt][3] + b1);
            if (CONV == 2) {
                long o0 = ((long)(n * 128 + co0) * 128 + y0) * 128 + px;
                long o1 = ((long)(n * 128 + co0 + 8) * 128 + y0) * 128 + px;
                *(float2*)&out[o0] = make_float2(v00, v01);
                *(float2*)&out[o1] = make_float2(v10, v11);
            } else {
                int y = y0 + (px >> 6), x = px & 63;
                const float S2 = 1.41421356237309515f;
                float vv[4] = {v00 * S2, v01 * S2, v10 * S2, v11 * S2};
                int cc2[4]  = {co0, co0, co0 + 8, co0 + 8};
                int xx2[4]  = {x, x + 1, x, x + 1};
                #pragma unroll
                for (int q = 0; q < 4; q++) {
                    __nv_bfloat16 h, l; bsplit(vv[q], h, l);
                    long o = ((long)(n * 64 + y) * 64 + xx2[q]) * 256 + cc2[q];
                    ((__nv_bfloat16*)g_o1_h)[o] = h;
                    ((__nv_bfloat16*)g_o1_l)[o] = l;
                }
            }
        }
    }
}

// ---------------------------------------------------------------------------
// final: out += upsampled-skip * (1/sqrt(2))
// ---------------------------------------------------------------------------
__global__ __launch_bounds__(256)
void skipadd_k(float* __restrict__ out)
{
    int idx = blockIdx.x * 256 + threadIdx.x;   // 4,194,304
    int xg = idx & 31, y = (idx >> 5) & 127, co = (idx >> 12) & 127, n = idx >> 19;

    int jy = y >> 1; bool ev = !(y & 1);
    int ya = ev ? max(jy - 1, 0) : jy;
    int yb = ev ? jy : min(jy + 1, 63);
    float wya = ev ? 0.25f : 0.75f, wyb = ev ? 0.75f : 0.25f;

    const float* S = g_skip + (long)(n * 128 + co) * 4096;
    int jxb = xg * 2 - 1;
    float rA[4], rB[4];
    #pragma unroll
    for (int k = 0; k < 4; k++) {
        int c = min(max(jxb + k, 0), 63);
        rA[k] = S[ya * 64 + c];
        rB[k] = S[yb * 64 + c];
    }
    long o = (((long)(n * 128 + co) * 128 + y) * 128 + xg * 4);
    float4 v = *(float4*)&out[o];
    float* ov = &v.x;
    #pragma unroll
    for (int p = 0; p < 4; p++) {
        int k0 = p >> 1;
        float sxA, sxB;
        if ((p & 1) == 0) {
            sxA = 0.25f * rA[k0] + 0.75f * rA[k0 + 1];
            sxB = 0.25f * rB[k0] + 0.75f * rB[k0 + 1];
        } else {
            sxA = 0.75f * rA[k0 + 1] + 0.25f * rA[k0 + 2];
            sxB = 0.75f * rB[k0 + 1] + 0.25f * rB[k0 + 2];
        }
        ov[p] += (wya * sxA + wyb * sxB) * 0.70710678118654752f;
    }
    *(float4*)&out[o] = v;
}

// ---------------------------------------------------------------------------
// kernel_launch — kernel launches only (graph-capturable, allocation-free)
// ---------------------------------------------------------------------------
extern "C" void kernel_launch(void* const* d_in, const int* in_sizes, int n_in,
                              void* d_out, int out_size)
{
    const float* x   = (const float*)d_in[0];
    const float* w1  = (const float*)d_in[1];
    const float* b1  = (const float*)d_in[2];
    const float* w2  = (const float*)d_in[3];
    const float* b2  = (const float*)d_in[4];
    const float* wsk = (const float*)d_in[5];
    float* out = (float*)d_out;

    prep_k<<<1024, 256>>>(w1, w2, wsk);
    convert_x_k<<<dim3(64, 8), 256>>>(x);
    skip1x1_v3<<<dim3(16, 2, 8), 256>>>(x);
    convmma_k<1><<<dim3(32, 4, 8), 256>>>(b1, nullptr);
    upsample_k<<<2048, 256>>>();
    convmma_k<2><<<dim3(128, 2, 8), 256>>>(b2, out);
    skipadd_k<<<16384, 256>>>(out);
}